// round 15
// baseline (speedup 1.0000x reference)
#include <cuda_runtime.h>
#include <cuda_fp16.h>
#include <math.h>

// ---------------------------------------------------------------------------
// MegatronAttention B=2,S=2048,H=2048,NH=16,DH=128 — mma.sync pure-fp16 GEMMs
// R14: CTA decoupling — 4 CTAs/SM of 4 warps each (CTA 128x64, warp 64x32,
// KC=64 SW128, PIPE=2, 49KB smem). 16 warps/SM in 4 independent barrier
// domains. exp-scores fp16 path from R13 unchanged.
// out quirk: einsum 'bhqk,bhkd->bhkd' sums q -> out = v * colsum(softmax).
// ---------------------------------------------------------------------------
#define SEQ 2048
#define HDIM 2048
#define NH 16
#define DHEAD 128
#define MR 4096               // B*S
#define QN 6144               // 3*NH*DH
#define NBH 32
#define NTILES 64             // 2048/32 score col-tiles per row

typedef long long ll;
typedef unsigned int u32;

// --------------------------- scratch buffers -------------------------------
__device__ __half g_x16[(size_t)MR*HDIM];
__device__ __half g_wqT[(size_t)QN*HDIM];
__device__ __half g_woT[(size_t)HDIM*HDIM];
__device__ __half g_qkv[(size_t)MR*QN];
__device__ __half g_scores[(size_t)NBH*SEQ*SEQ];     // exp(s - pm_tile), fp16
__device__ __half g_v16[(size_t)MR*HDIM];
__device__ float g_pmax[(size_t)NBH*SEQ*NTILES], g_psum[(size_t)NBH*SEQ*NTILES];
__device__ float g_w[(size_t)NBH*SEQ*NTILES];        // exp(pm-gm)/z per (row,tile)
__device__ float g_colsum[NBH*SEQ];

// --------------------------- helpers ---------------------------------------
__device__ __forceinline__ u32 s2u(const void* p){
    u32 a; asm("{ .reg .u64 t; cvta.to.shared.u64 t, %1; cvt.u32.u64 %0, t; }":"=r"(a):"l"(p)); return a;
}
#define SWZ128(o) ((o) ^ (((o)>>3)&0x70))

__device__ __forceinline__ void cpa16(u32 d, const void* s){
    asm volatile("cp.async.cg.shared.global [%0], [%1], 16;" :: "r"(d), "l"(s));
}
__device__ __forceinline__ void cpc(){ asm volatile("cp.async.commit_group;"); }
template<int N> __device__ __forceinline__ void cpw(){ asm volatile("cp.async.wait_group %0;"::"n"(N)); }

__device__ __forceinline__ void ldm4(u32* r, u32 addr){
    asm volatile("ldmatrix.sync.aligned.m8n8.x4.shared.b16 {%0,%1,%2,%3}, [%4];"
        : "=r"(r[0]),"=r"(r[1]),"=r"(r[2]),"=r"(r[3]) : "r"(addr));
}
__device__ __forceinline__ void mma16816(float* d, const u32* a, u32 b0, u32 b1){
    asm volatile("mma.sync.aligned.m16n8k16.row.col.f32.f16.f16.f32 "
        "{%0,%1,%2,%3}, {%4,%5,%6,%7}, {%8,%9}, {%0,%1,%2,%3};"
        : "+f"(d[0]),"+f"(d[1]),"+f"(d[2]),"+f"(d[3])
        : "r"(a[0]),"r"(a[1]),"r"(a[2]),"r"(a[3]), "r"(b0),"r"(b1));
}

// --------------------------- mma.sync GEMM ---------------------------------
// CTA 128x64, 4 warps (2x2 of 64x32), KC=64, PIPE=2, 4 CTAs/SM.
#define KC 64
#define A_TILE_B 16384            // 128 rows x 128B
#define B_TILE_B 8192             // 64 rows x 128B
#define STAGE_BYTES (A_TILE_B + B_TILE_B)   // 24KB
#define PIPE 2
#define GSMEM_SZ (1024 + PIPE*STAGE_BYTES)  // ~49KB -> 4 CTAs/SM

// EPI: 0 = f32 out, 1 = fp16 out, 2 = fp16 exp-scores + partial softmax
template<int EPI, int K, int LDA, int LDB, int LDC, int ZDIV,
         ll SAO, ll SAI, ll SBO, ll SBI, ll SCO, ll SCI>
__global__ __launch_bounds__(128, 4)
void gemm_mma(const __half* __restrict__ A16, const __half* __restrict__ B16,
              float* __restrict__ Cf, __half* __restrict__ C16,
              float* __restrict__ Pm, float* __restrict__ Ps, float alpha)
{
    extern __shared__ char smem[];
    const u32 stage0 = (s2u(smem) + 1023u) & ~1023u;
    const int tid = threadIdx.x;
    const int lane = tid & 31;
    const int wid = tid >> 5;              // 0..3
    const int wm = (wid & 1) * 64;         // 2 warp-rows of 64
    const int wn = (wid >> 1) * 32;        // 2 warp-cols of 32
    const int lrow16 = lane & 15;
    const int lcol16 = (lane >> 4) * 16;

    const int zo = blockIdx.z / ZDIV, zi = blockIdx.z % ZDIV;
    const ll aoff = zo*SAO + zi*SAI;
    const ll boff = zo*SBO + zi*SBI;
    const ll coff = zo*SCO + zi*SCI;

    const int m0 = blockIdx.y * 128;
    const int n0 = blockIdx.x * 64;
    const int NK = K / KC;

    // hoisted swizzled ldmatrix offsets (k16 toggles via ^(k16*32))
    u32 aofs[4], bofs[2];
    #pragma unroll
    for (int mf = 0; mf < 4; mf++)
        aofs[mf] = SWZ128((u32)((wm + mf*16 + lrow16)*128 + lcol16));
    #pragma unroll
    for (int n2 = 0; n2 < 2; n2++)
        bofs[n2] = SWZ128((u32)((wn + n2*16 + lrow16)*128 + lcol16));

    // loader: A 1 thread/row (8x16B); B 2 threads/row (4x16B each)
    const __half* pA = A16 + aoff + (ll)(m0 + tid)*LDA;
    const __half* pB = B16 + boff + (ll)(n0 + (tid >> 1))*LDB + (tid & 1)*32;

    auto fetch = [&](int s){
        const u32 base = stage0 + (s & 1) * STAGE_BYTES;
        #pragma unroll
        for (int j = 0; j < 8; j++)
            cpa16(base + SWZ128((u32)(tid*128 + j*16)), pA + j*8);
        #pragma unroll
        for (int j = 0; j < 4; j++)
            cpa16(base + A_TILE_B + SWZ128((u32)((tid>>1)*128 + ((tid&1)*4 + j)*16)), pB + j*8);
        cpc();
        pA += KC; pB += KC;
    };

    float acc[4][4][4];
    #pragma unroll
    for (int i=0;i<4;i++)
    #pragma unroll
    for (int j=0;j<4;j++)
    #pragma unroll
    for (int r=0;r<4;r++) acc[i][j][r] = 0.f;

    int fetched = 0;
    for (; fetched < PIPE-1 && fetched < NK; fetched++) fetch(fetched);

    for (int kc = 0; kc < NK; kc++) {
        const int pend = fetched - kc - 1;
        if (pend <= 0) cpw<0>(); else cpw<1>();
        __syncthreads();
        if (fetched < NK) { fetch(fetched); fetched++; }

        const u32 sb = stage0 + (kc & 1) * STAGE_BYTES;
        const u32 sA = sb, sB = sb + A_TILE_B;

        #pragma unroll
        for (int k16 = 0; k16 < 4; k16++) {
            const u32 kx = (u32)(k16 * 32);
            u32 a4[4][4], bh[2][4];
            #pragma unroll
            for (int n2 = 0; n2 < 2; n2++)
                ldm4(bh[n2], sB + (bofs[n2] ^ kx));
            #pragma unroll
            for (int mf = 0; mf < 4; mf++)
                ldm4(a4[mf], sA + (aofs[mf] ^ kx));
            #pragma unroll
            for (int n2 = 0; n2 < 2; n2++)
            #pragma unroll
            for (int od = 0; od < 2; od++) {
                const int nf = n2*2 + od;
                #pragma unroll
                for (int mf = 0; mf < 4; mf++)
                    mma16816(acc[mf][nf], a4[mf], bh[n2][od], bh[n2][od+2]);
            }
        }
    }

    const int g = lane >> 2, tig = lane & 3;

    if (EPI == 2) {
        // stats + in-place transform acc -> exp((s - mx)*alpha), store fp16
        const int bh_ = blockIdx.z;
        const int nt = (n0 + wn) >> 5;
        #pragma unroll
        for (int mf = 0; mf < 4; mf++) {
            #pragma unroll
            for (int half = 0; half < 2; half++) {
                const int r0i = half * 2;
                float mx = -1e30f;
                #pragma unroll
                for (int nf = 0; nf < 4; nf++)
                    mx = fmaxf(mx, fmaxf(acc[mf][nf][r0i], acc[mf][nf][r0i+1]));
                mx = fmaxf(mx, __shfl_xor_sync(0xffffffffu, mx, 1));
                mx = fmaxf(mx, __shfl_xor_sync(0xffffffffu, mx, 2));
                float sm = 0.f;
                #pragma unroll
                for (int nf = 0; nf < 4; nf++) {
                    float e0 = __expf((acc[mf][nf][r0i]   - mx)*alpha);
                    float e1 = __expf((acc[mf][nf][r0i+1] - mx)*alpha);
                    acc[mf][nf][r0i] = e0; acc[mf][nf][r0i+1] = e1;
                    sm += e0 + e1;
                }
                sm += __shfl_xor_sync(0xffffffffu, sm, 1);
                sm += __shfl_xor_sync(0xffffffffu, sm, 2);
                if (tig == 0) {
                    const int row = m0 + wm + mf*16 + g + half*8;
                    const ll idx = ((ll)bh_*SEQ + row)*NTILES + nt;
                    Pm[idx] = mx*alpha; Ps[idx] = sm;
                }
            }
        }
        #pragma unroll
        for (int mf = 0; mf < 4; mf++) {
            #pragma unroll
            for (int nf = 0; nf < 4; nf++) {
                const ll m = m0 + wm + mf*16 + g;
                const int n = n0 + wn + nf*8 + tig*2;
                __half2 h01 = __halves2half2(__float2half(acc[mf][nf][0]), __float2half(acc[mf][nf][1]));
                __half2 h23 = __halves2half2(__float2half(acc[mf][nf][2]), __float2half(acc[mf][nf][3]));
                *reinterpret_cast<u32*>(C16 + coff + m*LDC + n) = *reinterpret_cast<u32*>(&h01);
                *reinterpret_cast<u32*>(C16 + coff + (m+8)*LDC + n) = *reinterpret_cast<u32*>(&h23);
            }
        }
    } else {
        #pragma unroll
        for (int mf = 0; mf < 4; mf++) {
            #pragma unroll
            for (int nf = 0; nf < 4; nf++) {
                const ll m = m0 + wm + mf*16 + g;
                const int n = n0 + wn + nf*8 + tig*2;
                float v0 = acc[mf][nf][0]*alpha, v1 = acc[mf][nf][1]*alpha;
                float v2 = acc[mf][nf][2]*alpha, v3 = acc[mf][nf][3]*alpha;
                if (EPI == 0) {
                    float2 v01 = {v0, v1}, v23 = {v2, v3};
                    *reinterpret_cast<float2*>(Cf + coff + m*LDC + n) = v01;
                    *reinterpret_cast<float2*>(Cf + coff + (m+8)*LDC + n) = v23;
                } else {
                    __half2 h01 = __halves2half2(__float2half(v0), __float2half(v1));
                    __half2 h23 = __halves2half2(__float2half(v2), __float2half(v3));
                    *reinterpret_cast<u32*>(C16 + coff + m*LDC + n) = *reinterpret_cast<u32*>(&h01);
                    *reinterpret_cast<u32*>(C16 + coff + (m+8)*LDC + n) = *reinterpret_cast<u32*>(&h23);
                }
            }
        }
    }
}

// --------------------------- prep kernels ----------------------------------
__global__ __launch_bounds__(256)
void round_x_kernel(const float* __restrict__ x, __half* __restrict__ o16)
{
    const ll i = ((ll)blockIdx.x * 256 + threadIdx.x) * 4;
    float4 v = *reinterpret_cast<const float4*>(x + i);
    __half2 a = __halves2half2(__float2half(v.x), __float2half(v.y));
    __half2 b = __halves2half2(__float2half(v.z), __float2half(v.w));
    *reinterpret_cast<__half2*>(o16 + i)     = a;
    *reinterpret_cast<__half2*>(o16 + i + 2) = b;
}

// in [R,C] f32 -> out [C,R] fp16 (rounded)
__global__ __launch_bounds__(256)
void transpose_round_kernel(const float* __restrict__ in, __half* __restrict__ o16,
                            int R, int C)
{
    __shared__ float t[32][33];
    const int c0 = blockIdx.x * 32, r0 = blockIdx.y * 32;
    const int tx = threadIdx.x, ty = threadIdx.y;
    #pragma unroll
    for (int i = 0; i < 4; i++)
        t[ty + 8*i][tx] = in[(ll)(r0 + ty + 8*i) * C + c0 + tx];
    __syncthreads();
    #pragma unroll
    for (int i = 0; i < 4; i++) {
        const ll o = (ll)(c0 + ty + 8*i) * R + r0 + tx;
        o16[o] = __float2half(t[tx][ty + 8*i]);
    }
}

// --------------------------- stats combine ---------------------------------
// one warp per row: combine 64 (pmax, psum) partials -> W[row, nt] = exp(pm-gm)/z
__global__ __launch_bounds__(256)
void stats_combine_kernel(const float* __restrict__ Pm, const float* __restrict__ Ps,
                          float* __restrict__ W)
{
    const int row = blockIdx.x * 8 + (threadIdx.x >> 5);
    const int lane = threadIdx.x & 31;
    float m1 = Pm[(ll)row*NTILES + lane];
    float m2 = Pm[(ll)row*NTILES + 32 + lane];
    float s1 = Ps[(ll)row*NTILES + lane];
    float s2 = Ps[(ll)row*NTILES + 32 + lane];
    float gm = fmaxf(m1, m2);
    #pragma unroll
    for (int o = 16; o; o >>= 1) gm = fmaxf(gm, __shfl_xor_sync(0xffffffffu, gm, o));
    float z = s1 * __expf(m1 - gm) + s2 * __expf(m2 - gm);
    #pragma unroll
    for (int o = 16; o; o >>= 1) z += __shfl_xor_sync(0xffffffffu, z, o);
    float inv = 1.0f / z;
    W[(ll)row*NTILES + lane]      = __expf(m1 - gm) * inv;
    W[(ll)row*NTILES + 32 + lane] = __expf(m2 - gm) * inv;
}

// colsum[k] = sum_q S'[q,k] * W[q, k/32]; 8 halves (uint4) per thread
__global__ __launch_bounds__(256)
void colsum4_kernel(const uint4* __restrict__ S8, const float* __restrict__ W,
                    float* __restrict__ colsum)
{
    const int bh = blockIdx.y;
    const int k8 = blockIdx.x * 256 + threadIdx.x;      // half8 index, 0..255
    const int q0 = blockIdx.z * 128;
    const uint4* sp = S8 + ((ll)bh*SEQ + q0)*(SEQ/8) + k8;
    const float* wp = W + ((ll)bh*SEQ + q0)*NTILES + (k8 >> 2);
    float a[8] = {0,0,0,0,0,0,0,0};
    #pragma unroll 4
    for (int q = 0; q < 128; q++) {
        float w = __ldg(wp + q*NTILES);
        uint4 sv = sp[(ll)q*(SEQ/8)];
        const __half2* h2 = reinterpret_cast<const __half2*>(&sv);
        #pragma unroll
        for (int j = 0; j < 4; j++) {
            float2 f = __half22float2(h2[j]);
            a[2*j]   += f.x*w;
            a[2*j+1] += f.y*w;
        }
    }
    float* cs = colsum + bh*SEQ + k8*8;
    #pragma unroll
    for (int j = 0; j < 8; j++) atomicAdd(cs+j, a[j]);
}

// vals = v * colsum -> fp16, half2 x4 vectorized
__global__ __launch_bounds__(256)
void scale_v_kernel(const __half* __restrict__ qkv, const float* __restrict__ colsum,
                    __half* __restrict__ v16)
{
    const ll i8 = ((ll)blockIdx.x * 256 + threadIdx.x) * 8;
    const int col = (int)(i8 & (HDIM - 1));
    const int row = (int)(i8 >> 11);
    const int h = col >> 7;
    const int b = row >> 11;
    const int s = row & (SEQ - 1);
    const float cs = colsum[(b*NH + h)*SEQ + s];
    const ll qo = (ll)row * QN + 2*NH*DHEAD + col;
    uint4 qv = *reinterpret_cast<const uint4*>(qkv + qo);
    const __half2* h2 = reinterpret_cast<const __half2*>(&qv);
    uint4 ov;
    __half2* o2 = reinterpret_cast<__half2*>(&ov);
    #pragma unroll
    for (int j = 0; j < 4; j++) {
        float2 f = __half22float2(h2[j]);
        o2[j] = __halves2half2(__float2half(f.x*cs), __float2half(f.y*cs));
    }
    *reinterpret_cast<uint4*>(v16 + i8) = ov;
}

// ---------------------------------------------------------------------------
extern "C" void kernel_launch(void* const* d_in, const int* in_sizes, int n_in,
                              void* d_out, int out_size)
{
    const float* x     = (const float*)d_in[0];
    const float* w_qkv = (const float*)d_in[1];
    const float* w_o   = (const float*)d_in[2];
    float* out = (float*)d_out;

    __half *x16,*wq,*wo,*qkv,*v16,*scores;
    float *colsum,*pmax,*psum,*wbuf;
    cudaGetSymbolAddress((void**)&x16, g_x16);
    cudaGetSymbolAddress((void**)&wq,  g_wqT);   cudaGetSymbolAddress((void**)&wo,  g_woT);
    cudaGetSymbolAddress((void**)&qkv, g_qkv);
    cudaGetSymbolAddress((void**)&v16, g_v16);
    cudaGetSymbolAddress((void**)&scores, g_scores);
    cudaGetSymbolAddress((void**)&colsum, g_colsum);
    cudaGetSymbolAddress((void**)&pmax, g_pmax);
    cudaGetSymbolAddress((void**)&psum, g_psum);
    cudaGetSymbolAddress((void**)&wbuf, g_w);

    auto k_qkv = gemm_mma<1, HDIM, HDIM, HDIM, QN, 1, 0,0,0,0,0,0>;
    auto k_sc  = gemm_mma<2, DHEAD, QN, QN, SEQ, NH,
                          (ll)SEQ*QN, 128, (ll)SEQ*QN, 128,
                          (ll)NH*SEQ*SEQ, (ll)SEQ*SEQ>;
    auto k_out = gemm_mma<0, HDIM, HDIM, HDIM, HDIM, 1, 0,0,0,0,0,0>;
    cudaFuncSetAttribute(k_qkv, cudaFuncAttributeMaxDynamicSharedMemorySize, GSMEM_SZ);
    cudaFuncSetAttribute(k_sc,  cudaFuncAttributeMaxDynamicSharedMemorySize, GSMEM_SZ);
    cudaFuncSetAttribute(k_out, cudaFuncAttributeMaxDynamicSharedMemorySize, GSMEM_SZ);

    // prep: round x, round+transpose weights
    round_x_kernel<<<(MR*HDIM)/1024, 256>>>(x, x16);
    transpose_round_kernel<<<dim3(QN/32, HDIM/32), dim3(32,8)>>>(w_qkv, wq, HDIM, QN);
    transpose_round_kernel<<<dim3(HDIM/32, HDIM/32), dim3(32,8)>>>(w_o, wo, HDIM, HDIM);

    // 1) qkv = x @ w_qkv (fp16 out)
    k_qkv<<<dim3(QN/64, MR/128, 1), 128, GSMEM_SZ>>>(
        x16, wq, nullptr, qkv, nullptr, nullptr, 1.0f);

    // 2) fp16 exp-scores + partial softmax stats, z = b*16+h
    k_sc<<<dim3(SEQ/64, SEQ/128, NBH), 128, GSMEM_SZ>>>(
        qkv, qkv + NH*DHEAD, nullptr, scores,
        pmax, psum, 0.08838834764831845f);

    // 3) combine partial stats -> per-(row,tile) weights
    stats_combine_kernel<<<(NBH*SEQ)/8, 256>>>(pmax, psum, wbuf);

    // 4) colsum = sum_q S' * W  (fp16 stream, fp32 accum)
    cudaMemsetAsync(colsum, 0, NBH*SEQ*sizeof(float));
    colsum4_kernel<<<dim3(SEQ/2048, NBH, SEQ/128), 256>>>(
        (const uint4*)scores, wbuf, colsum);

    // 5) vals = v * colsum (fp16)
    scale_v_kernel<<<(MR*HDIM)/2048, 256>>>(qkv, colsum, v16);

    // 6) out = vals @ w_o
    k_out<<<dim3(HDIM/64, MR/128, 1), 128, GSMEM_SZ>>>(
        v16, wo, out, nullptr, nullptr, nullptr, 1.0f);
}

// round 16
// speedup vs baseline: 1.3289x; 1.3289x over previous
#include <cuda_runtime.h>
#include <cuda_fp16.h>
#include <math.h>

// ---------------------------------------------------------------------------
// MegatronAttention B=2,S=2048,H=2048,NH=16,DH=128 — mma.sync pure-fp16 GEMMs
// R15: R13 config restored (8 warps, warp 64x32, CTA 128x128, KC=64 SW128,
// PIPE=3, 2 CTAs/SM) + A-loads via cp.async.ca (twin-CTA L1 sharing) +
// colsum q-chunk 64 (2x blocks). exp-scores fp16.
// out quirk: einsum 'bhqk,bhkd->bhkd' sums q -> out = v * colsum(softmax).
// ---------------------------------------------------------------------------
#define SEQ 2048
#define HDIM 2048
#define NH 16
#define DHEAD 128
#define MR 4096               // B*S
#define QN 6144               // 3*NH*DH
#define NBH 32
#define NTILES 64             // 2048/32 score col-tiles per row

typedef long long ll;
typedef unsigned int u32;

// --------------------------- scratch buffers -------------------------------
__device__ __half g_x16[(size_t)MR*HDIM];
__device__ __half g_wqT[(size_t)QN*HDIM];
__device__ __half g_woT[(size_t)HDIM*HDIM];
__device__ __half g_qkv[(size_t)MR*QN];
__device__ __half g_scores[(size_t)NBH*SEQ*SEQ];     // exp(s - pm_tile), fp16
__device__ __half g_v16[(size_t)MR*HDIM];
__device__ float g_pmax[(size_t)NBH*SEQ*NTILES], g_psum[(size_t)NBH*SEQ*NTILES];
__device__ float g_w[(size_t)NBH*SEQ*NTILES];        // exp(pm-gm)/z per (row,tile)
__device__ float g_colsum[NBH*SEQ];

// --------------------------- helpers ---------------------------------------
__device__ __forceinline__ u32 s2u(const void* p){
    u32 a; asm("{ .reg .u64 t; cvta.to.shared.u64 t, %1; cvt.u32.u64 %0, t; }":"=r"(a):"l"(p)); return a;
}
#define SWZ128(o) ((o) ^ (((o)>>3)&0x70))

__device__ __forceinline__ void cpa16_cg(u32 d, const void* s){
    asm volatile("cp.async.cg.shared.global [%0], [%1], 16;" :: "r"(d), "l"(s));
}
__device__ __forceinline__ void cpa16_ca(u32 d, const void* s){
    asm volatile("cp.async.ca.shared.global [%0], [%1], 16;" :: "r"(d), "l"(s));
}
__device__ __forceinline__ void cpc(){ asm volatile("cp.async.commit_group;"); }
template<int N> __device__ __forceinline__ void cpw(){ asm volatile("cp.async.wait_group %0;"::"n"(N)); }

__device__ __forceinline__ void ldm4(u32* r, u32 addr){
    asm volatile("ldmatrix.sync.aligned.m8n8.x4.shared.b16 {%0,%1,%2,%3}, [%4];"
        : "=r"(r[0]),"=r"(r[1]),"=r"(r[2]),"=r"(r[3]) : "r"(addr));
}
__device__ __forceinline__ void mma16816(float* d, const u32* a, u32 b0, u32 b1){
    asm volatile("mma.sync.aligned.m16n8k16.row.col.f32.f16.f16.f32 "
        "{%0,%1,%2,%3}, {%4,%5,%6,%7}, {%8,%9}, {%0,%1,%2,%3};"
        : "+f"(d[0]),"+f"(d[1]),"+f"(d[2]),"+f"(d[3])
        : "r"(a[0]),"r"(a[1]),"r"(a[2]),"r"(a[3]), "r"(b0),"r"(b1));
}

// --------------------------- mma.sync GEMM ---------------------------------
#define KC 64
#define TILE_B 16384              // 128 rows x 128B
#define STAGE_BYTES (2*TILE_B)    // A, B = 32KB
#define PIPE 3
#define GSMEM_SZ (1024 + PIPE*STAGE_BYTES)   // ~97KB -> 2 CTAs/SM

// EPI: 0 = f32 out, 1 = fp16 out, 2 = fp16 exp-scores + partial softmax
template<int EPI, int K, int LDA, int LDB, int LDC, int ZDIV,
         ll SAO, ll SAI, ll SBO, ll SBI, ll SCO, ll SCI>
__global__ __launch_bounds__(256, 2)
void gemm_mma(const __half* __restrict__ A16, const __half* __restrict__ B16,
              float* __restrict__ Cf, __half* __restrict__ C16,
              float* __restrict__ Pm, float* __restrict__ Ps, float alpha)
{
    extern __shared__ char smem[];
    const u32 stage0 = (s2u(smem) + 1023u) & ~1023u;
    const int tid = threadIdx.x;
    const int lane = tid & 31;
    const int wid = tid >> 5;
    const int wm = (wid & 1) * 64;
    const int wn = (wid >> 1) * 32;
    const int lrow16 = lane & 15;
    const int lcol16 = (lane >> 4) * 16;

    const int zo = blockIdx.z / ZDIV, zi = blockIdx.z % ZDIV;
    const ll aoff = zo*SAO + zi*SAI;
    const ll boff = zo*SBO + zi*SBI;
    const ll coff = zo*SCO + zi*SCI;

    const int m0 = blockIdx.y * 128;
    const int n0 = blockIdx.x * 128;
    const int NK = K / KC;

    // hoisted swizzled ldmatrix offsets (k16 toggles via ^(k16*32))
    u32 aofs[4], bofs[2];
    #pragma unroll
    for (int mf = 0; mf < 4; mf++)
        aofs[mf] = SWZ128((u32)((wm + mf*16 + lrow16)*128 + lcol16));
    #pragma unroll
    for (int n2 = 0; n2 < 2; n2++)
        bofs[n2] = SWZ128((u32)((wn + n2*16 + lrow16)*128 + lcol16));

    // loader: 2 threads per row, 4x16B each; tile = 128 rows x 128B
    const int arow = tid >> 1;
    const int aseg = (tid & 1) * 4;
    const __half* pA = A16 + aoff + (ll)(m0 + arow)*LDA + aseg*8;
    const __half* pB = B16 + boff + (ll)(n0 + arow)*LDB + aseg*8;
    u32 ld_d[4];
    #pragma unroll
    for (int j = 0; j < 4; j++) ld_d[j] = SWZ128((u32)(arow*128 + (aseg + j)*16));

    auto fetch = [&](int s){
        const u32 base = stage0 + (s % PIPE) * STAGE_BYTES;
        #pragma unroll
        for (int j = 0; j < 4; j++) cpa16_ca(base + ld_d[j],          pA + j*8);
        #pragma unroll
        for (int j = 0; j < 4; j++) cpa16_cg(base + TILE_B + ld_d[j], pB + j*8);
        cpc();
        pA += KC; pB += KC;
    };

    float acc[4][4][4];
    #pragma unroll
    for (int i=0;i<4;i++)
    #pragma unroll
    for (int j=0;j<4;j++)
    #pragma unroll
    for (int r=0;r<4;r++) acc[i][j][r] = 0.f;

    int fetched = 0;
    for (; fetched < PIPE-1 && fetched < NK; fetched++) fetch(fetched);

    for (int kc = 0; kc < NK; kc++) {
        const int pend = fetched - kc - 1;
        if (pend <= 0) cpw<0>(); else if (pend == 1) cpw<1>(); else cpw<2>();
        __syncthreads();
        if (fetched < NK) { fetch(fetched); fetched++; }

        const u32 sb = stage0 + (kc % PIPE) * STAGE_BYTES;
        const u32 sA = sb, sB = sb + TILE_B;

        #pragma unroll
        for (int k16 = 0; k16 < 4; k16++) {
            const u32 kx = (u32)(k16 * 32);
            u32 a4[4][4], bh[2][4];
            #pragma unroll
            for (int n2 = 0; n2 < 2; n2++)
                ldm4(bh[n2], sB + (bofs[n2] ^ kx));
            #pragma unroll
            for (int mf = 0; mf < 4; mf++)
                ldm4(a4[mf], sA + (aofs[mf] ^ kx));
            #pragma unroll
            for (int n2 = 0; n2 < 2; n2++)
            #pragma unroll
            for (int od = 0; od < 2; od++) {
                const int nf = n2*2 + od;
                #pragma unroll
                for (int mf = 0; mf < 4; mf++)
                    mma16816(acc[mf][nf], a4[mf], bh[n2][od], bh[n2][od+2]);
            }
        }
    }

    const int g = lane >> 2, tig = lane & 3;

    if (EPI == 2) {
        // stats + in-place transform acc -> exp((s - mx)*alpha), store fp16
        const int bh_ = blockIdx.z;
        const int nt = (n0 + wn) >> 5;
        #pragma unroll
        for (int mf = 0; mf < 4; mf++) {
            #pragma unroll
            for (int half = 0; half < 2; half++) {
                const int r0i = half * 2;
                float mx = -1e30f;
                #pragma unroll
                for (int nf = 0; nf < 4; nf++)
                    mx = fmaxf(mx, fmaxf(acc[mf][nf][r0i], acc[mf][nf][r0i+1]));
                mx = fmaxf(mx, __shfl_xor_sync(0xffffffffu, mx, 1));
                mx = fmaxf(mx, __shfl_xor_sync(0xffffffffu, mx, 2));
                float sm = 0.f;
                #pragma unroll
                for (int nf = 0; nf < 4; nf++) {
                    float e0 = __expf((acc[mf][nf][r0i]   - mx)*alpha);
                    float e1 = __expf((acc[mf][nf][r0i+1] - mx)*alpha);
                    acc[mf][nf][r0i] = e0; acc[mf][nf][r0i+1] = e1;
                    sm += e0 + e1;
                }
                sm += __shfl_xor_sync(0xffffffffu, sm, 1);
                sm += __shfl_xor_sync(0xffffffffu, sm, 2);
                if (tig == 0) {
                    const int row = m0 + wm + mf*16 + g + half*8;
                    const ll idx = ((ll)bh_*SEQ + row)*NTILES + nt;
                    Pm[idx] = mx*alpha; Ps[idx] = sm;
                }
            }
        }
        #pragma unroll
        for (int mf = 0; mf < 4; mf++) {
            #pragma unroll
            for (int nf = 0; nf < 4; nf++) {
                const ll m = m0 + wm + mf*16 + g;
                const int n = n0 + wn + nf*8 + tig*2;
                __half2 h01 = __halves2half2(__float2half(acc[mf][nf][0]), __float2half(acc[mf][nf][1]));
                __half2 h23 = __halves2half2(__float2half(acc[mf][nf][2]), __float2half(acc[mf][nf][3]));
                *reinterpret_cast<u32*>(C16 + coff + m*LDC + n) = *reinterpret_cast<u32*>(&h01);
                *reinterpret_cast<u32*>(C16 + coff + (m+8)*LDC + n) = *reinterpret_cast<u32*>(&h23);
            }
        }
    } else {
        #pragma unroll
        for (int mf = 0; mf < 4; mf++) {
            #pragma unroll
            for (int nf = 0; nf < 4; nf++) {
                const ll m = m0 + wm + mf*16 + g;
                const int n = n0 + wn + nf*8 + tig*2;
                float v0 = acc[mf][nf][0]*alpha, v1 = acc[mf][nf][1]*alpha;
                float v2 = acc[mf][nf][2]*alpha, v3 = acc[mf][nf][3]*alpha;
                if (EPI == 0) {
                    float2 v01 = {v0, v1}, v23 = {v2, v3};
                    *reinterpret_cast<float2*>(Cf + coff + m*LDC + n) = v01;
                    *reinterpret_cast<float2*>(Cf + coff + (m+8)*LDC + n) = v23;
                } else {
                    __half2 h01 = __halves2half2(__float2half(v0), __float2half(v1));
                    __half2 h23 = __halves2half2(__float2half(v2), __float2half(v3));
                    *reinterpret_cast<u32*>(C16 + coff + m*LDC + n) = *reinterpret_cast<u32*>(&h01);
                    *reinterpret_cast<u32*>(C16 + coff + (m+8)*LDC + n) = *reinterpret_cast<u32*>(&h23);
                }
            }
        }
    }
}

// --------------------------- prep kernels ----------------------------------
__global__ __launch_bounds__(256)
void round_x_kernel(const float* __restrict__ x, __half* __restrict__ o16)
{
    const ll i = ((ll)blockIdx.x * 256 + threadIdx.x) * 4;
    float4 v = *reinterpret_cast<const float4*>(x + i);
    __half2 a = __halves2half2(__float2half(v.x), __float2half(v.y));
    __half2 b = __halves2half2(__float2half(v.z), __float2half(v.w));
    *reinterpret_cast<__half2*>(o16 + i)     = a;
    *reinterpret_cast<__half2*>(o16 + i + 2) = b;
}

// in [R,C] f32 -> out [C,R] fp16 (rounded)
__global__ __launch_bounds__(256)
void transpose_round_kernel(const float* __restrict__ in, __half* __restrict__ o16,
                            int R, int C)
{
    __shared__ float t[32][33];
    const int c0 = blockIdx.x * 32, r0 = blockIdx.y * 32;
    const int tx = threadIdx.x, ty = threadIdx.y;
    #pragma unroll
    for (int i = 0; i < 4; i++)
        t[ty + 8*i][tx] = in[(ll)(r0 + ty + 8*i) * C + c0 + tx];
    __syncthreads();
    #pragma unroll
    for (int i = 0; i < 4; i++) {
        const ll o = (ll)(c0 + ty + 8*i) * R + r0 + tx;
        o16[o] = __float2half(t[tx][ty + 8*i]);
    }
}

// --------------------------- stats combine ---------------------------------
// one warp per row: combine 64 (pmax, psum) partials -> W[row, nt] = exp(pm-gm)/z
__global__ __launch_bounds__(256)
void stats_combine_kernel(const float* __restrict__ Pm, const float* __restrict__ Ps,
                          float* __restrict__ W)
{
    const int row = blockIdx.x * 8 + (threadIdx.x >> 5);
    const int lane = threadIdx.x & 31;
    float m1 = Pm[(ll)row*NTILES + lane];
    float m2 = Pm[(ll)row*NTILES + 32 + lane];
    float s1 = Ps[(ll)row*NTILES + lane];
    float s2 = Ps[(ll)row*NTILES + 32 + lane];
    float gm = fmaxf(m1, m2);
    #pragma unroll
    for (int o = 16; o; o >>= 1) gm = fmaxf(gm, __shfl_xor_sync(0xffffffffu, gm, o));
    float z = s1 * __expf(m1 - gm) + s2 * __expf(m2 - gm);
    #pragma unroll
    for (int o = 16; o; o >>= 1) z += __shfl_xor_sync(0xffffffffu, z, o);
    float inv = 1.0f / z;
    W[(ll)row*NTILES + lane]      = __expf(m1 - gm) * inv;
    W[(ll)row*NTILES + 32 + lane] = __expf(m2 - gm) * inv;
}

// colsum[k] = sum_q S'[q,k] * W[q, k/32]; 8 halves (uint4) per thread, q-chunk 64
__global__ __launch_bounds__(256)
void colsum4_kernel(const uint4* __restrict__ S8, const float* __restrict__ W,
                    float* __restrict__ colsum)
{
    const int bh = blockIdx.y;
    const int k8 = blockIdx.x * 256 + threadIdx.x;      // half8 index, 0..255
    const int q0 = blockIdx.z * 64;
    const uint4* sp = S8 + ((ll)bh*SEQ + q0)*(SEQ/8) + k8;
    const float* wp = W + ((ll)bh*SEQ + q0)*NTILES + (k8 >> 2);
    float a[8] = {0,0,0,0,0,0,0,0};
    #pragma unroll 4
    for (int q = 0; q < 64; q++) {
        float w = __ldg(wp + q*NTILES);
        uint4 sv = sp[(ll)q*(SEQ/8)];
        const __half2* h2 = reinterpret_cast<const __half2*>(&sv);
        #pragma unroll
        for (int j = 0; j < 4; j++) {
            float2 f = __half22float2(h2[j]);
            a[2*j]   += f.x*w;
            a[2*j+1] += f.y*w;
        }
    }
    float* cs = colsum + bh*SEQ + k8*8;
    #pragma unroll
    for (int j = 0; j < 8; j++) atomicAdd(cs+j, a[j]);
}

// vals = v * colsum -> fp16, half2 x4 vectorized
__global__ __launch_bounds__(256)
void scale_v_kernel(const __half* __restrict__ qkv, const float* __restrict__ colsum,
                    __half* __restrict__ v16)
{
    const ll i8 = ((ll)blockIdx.x * 256 + threadIdx.x) * 8;
    const int col = (int)(i8 & (HDIM - 1));
    const int row = (int)(i8 >> 11);
    const int h = col >> 7;
    const int b = row >> 11;
    const int s = row & (SEQ - 1);
    const float cs = colsum[(b*NH + h)*SEQ + s];
    const ll qo = (ll)row * QN + 2*NH*DHEAD + col;
    uint4 qv = *reinterpret_cast<const uint4*>(qkv + qo);
    const __half2* h2 = reinterpret_cast<const __half2*>(&qv);
    uint4 ov;
    __half2* o2 = reinterpret_cast<__half2*>(&ov);
    #pragma unroll
    for (int j = 0; j < 4; j++) {
        float2 f = __half22float2(h2[j]);
        o2[j] = __halves2half2(__float2half(f.x*cs), __float2half(f.y*cs));
    }
    *reinterpret_cast<uint4*>(v16 + i8) = ov;
}

// ---------------------------------------------------------------------------
extern "C" void kernel_launch(void* const* d_in, const int* in_sizes, int n_in,
                              void* d_out, int out_size)
{
    const float* x     = (const float*)d_in[0];
    const float* w_qkv = (const float*)d_in[1];
    const float* w_o   = (const float*)d_in[2];
    float* out = (float*)d_out;

    __half *x16,*wq,*wo,*qkv,*v16,*scores;
    float *colsum,*pmax,*psum,*wbuf;
    cudaGetSymbolAddress((void**)&x16, g_x16);
    cudaGetSymbolAddress((void**)&wq,  g_wqT);   cudaGetSymbolAddress((void**)&wo,  g_woT);
    cudaGetSymbolAddress((void**)&qkv, g_qkv);
    cudaGetSymbolAddress((void**)&v16, g_v16);
    cudaGetSymbolAddress((void**)&scores, g_scores);
    cudaGetSymbolAddress((void**)&colsum, g_colsum);
    cudaGetSymbolAddress((void**)&pmax, g_pmax);
    cudaGetSymbolAddress((void**)&psum, g_psum);
    cudaGetSymbolAddress((void**)&wbuf, g_w);

    auto k_qkv = gemm_mma<1, HDIM, HDIM, HDIM, QN, 1, 0,0,0,0,0,0>;
    auto k_sc  = gemm_mma<2, DHEAD, QN, QN, SEQ, NH,
                          (ll)SEQ*QN, 128, (ll)SEQ*QN, 128,
                          (ll)NH*SEQ*SEQ, (ll)SEQ*SEQ>;
    auto k_out = gemm_mma<0, HDIM, HDIM, HDIM, HDIM, 1, 0,0,0,0,0,0>;
    cudaFuncSetAttribute(k_qkv, cudaFuncAttributeMaxDynamicSharedMemorySize, GSMEM_SZ);
    cudaFuncSetAttribute(k_sc,  cudaFuncAttributeMaxDynamicSharedMemorySize, GSMEM_SZ);
    cudaFuncSetAttribute(k_out, cudaFuncAttributeMaxDynamicSharedMemorySize, GSMEM_SZ);

    // prep: round x, round+transpose weights
    round_x_kernel<<<(MR*HDIM)/1024, 256>>>(x, x16);
    transpose_round_kernel<<<dim3(QN/32, HDIM/32), dim3(32,8)>>>(w_qkv, wq, HDIM, QN);
    transpose_round_kernel<<<dim3(HDIM/32, HDIM/32), dim3(32,8)>>>(w_o, wo, HDIM, HDIM);

    // 1) qkv = x @ w_qkv (fp16 out)
    k_qkv<<<dim3(QN/128, MR/128, 1), 256, GSMEM_SZ>>>(
        x16, wq, nullptr, qkv, nullptr, nullptr, 1.0f);

    // 2) fp16 exp-scores + partial softmax stats, z = b*16+h
    k_sc<<<dim3(SEQ/128, SEQ/128, NBH), 256, GSMEM_SZ>>>(
        qkv, qkv + NH*DHEAD, nullptr, scores,
        pmax, psum, 0.08838834764831845f);

    // 3) combine partial stats -> per-(row,tile) weights
    stats_combine_kernel<<<(NBH*SEQ)/8, 256>>>(pmax, psum, wbuf);

    // 4) colsum = sum_q S' * W  (fp16 stream, fp32 accum, q-chunk 64)
    cudaMemsetAsync(colsum, 0, NBH*SEQ*sizeof(float));
    colsum4_kernel<<<dim3(SEQ/2048, NBH, SEQ/64), 256>>>(
        (const uint4*)scores, wbuf, colsum);

    // 5) vals = v * colsum (fp16)
    scale_v_kernel<<<(MR*HDIM)/2048, 256>>>(qkv, colsum, v16);

    // 6) out = vals @ w_o
    k_out<<<dim3(HDIM/128, MR/128, 1), 256, GSMEM_SZ>>>(
        v16, wo, out, nullptr, nullptr, nullptr, 1.0f);
}